// round 7
// baseline (speedup 1.0000x reference)
#include <cuda_runtime.h>
#include <cuda_fp16.h>
#include <stdint.h>

// Problem constants
#define Q_I     512
#define Q_O     32
#define Q_JD    8                  // dense degree slots (j=1..8; j=0 folded into bias)
#define Q_CHI   16                 // inputs per chunk
#define Q_CHK   128                // k per chunk (16*8) -> 8 k16 MMA steps
#define Q_NCH   32                 // 512/16
#define Q_ROWS  128                // batch rows per CTA
#define Q_THR   128                // 4 warps

// smem (halves): W [32][136] then basisT [128][136]
#define WPAD    136
#define BPAD    136
#define SM_W    0
#define SM_B    (Q_O * WPAD * 2)                  // 8704 bytes
#define SM_TOT  (SM_B + Q_CHK * BPAD * 2)         // 43520 bytes

// Repacked fp16 weights (j=1..8): g_W2[c][o][kl], kl = ip*8 + (j-1)
__device__ __half g_W2[Q_NCH * Q_O * Q_CHK];
__device__ float  g_bias[Q_O];

__global__ void repack_kernel(const float* __restrict__ w) {
    int idx = blockIdx.x * blockDim.x + threadIdx.x;
    if (idx >= Q_NCH * Q_O * Q_CHK) return;
    int kl = idx & 127;
    int o  = (idx >> 7) & 31;
    int c  = idx >> 12;
    int i  = c * Q_CHI + (kl >> 3);
    int j  = (kl & 7) + 1;
    g_W2[idx] = __float2half(w[(i * Q_O + o) * 9 + j]);
}

__global__ void bias_kernel(const float* __restrict__ w) {
    int o = threadIdx.x;              // 32 threads
    float s = 0.0f;
    for (int i = 0; i < Q_I; ++i) s += w[(i * Q_O + o) * 9];
    g_bias[o] = s;
}

// ---------------- primitives ----------------
__device__ __forceinline__ uint32_t smem_u32(const void* p) {
    uint32_t a;
    asm("{ .reg .u64 t; cvta.to.shared.u64 t, %1; cvt.u32.u64 %0, t; }" : "=r"(a) : "l"(p));
    return a;
}
__device__ __forceinline__ void ldm_x4(uint32_t (&r)[4], uint32_t addr) {
    asm volatile("ldmatrix.sync.aligned.m8n8.x4.shared.b16 {%0,%1,%2,%3}, [%4];"
                 : "=r"(r[0]), "=r"(r[1]), "=r"(r[2]), "=r"(r[3]) : "r"(addr));
}
__device__ __forceinline__ void ldm_x4_t(uint32_t (&r)[4], uint32_t addr) {
    asm volatile("ldmatrix.sync.aligned.m8n8.x4.trans.shared.b16 {%0,%1,%2,%3}, [%4];"
                 : "=r"(r[0]), "=r"(r[1]), "=r"(r[2]), "=r"(r[3]) : "r"(addr));
}
__device__ __forceinline__ void mma16816(float (&d)[4], const uint32_t (&a)[4],
                                         uint32_t b0, uint32_t b1) {
    asm volatile(
        "mma.sync.aligned.m16n8k16.row.col.f32.f16.f16.f32 "
        "{%0,%1,%2,%3}, {%4,%5,%6,%7}, {%8,%9}, {%0,%1,%2,%3};"
        : "+f"(d[0]), "+f"(d[1]), "+f"(d[2]), "+f"(d[3])
        : "r"(a[0]), "r"(a[1]), "r"(a[2]), "r"(a[3]), "r"(b0), "r"(b1));
}
__device__ __forceinline__ uint32_t pack2(float a, float b) {
    __half2 h = __floats2half2_rn(a, b);
    return *reinterpret_cast<uint32_t*>(&h);
}
// tanh(x) = 1 - 2/(exp2(2x*log2e)+1)
__device__ __forceinline__ float ftanh(float x) {
    float p;
    asm("ex2.approx.f32 %0, %1;" : "=f"(p) : "f"(x * 2.8853900817779268f));
    float r;
    asm("rcp.approx.f32 %0, %1;" : "=f"(r) : "f"(p + 1.0f));
    return fmaf(-2.0f, r, 1.0f);
}

__global__ __launch_bounds__(Q_THR)
void cheby_mma_kernel(const float* __restrict__ x, float* __restrict__ out) {
    extern __shared__ char smem[];
    const uint32_t sW = smem_u32(smem) + SM_W;
    const uint32_t sB = smem_u32(smem) + SM_B;
    __half* smW = reinterpret_cast<__half*>(smem + SM_W);

    const int t    = threadIdx.x;
    const int lane = t & 31;
    const int w    = t >> 5;             // warp id: rows [32w, 32w+32)
    const int b0   = blockIdx.x * Q_ROWS;

    // gen mapping (R4): thread owns row-pair (2rp, 2rp+1), inputs [ig*8, ig*8+8)
    const int rp = t & 63;
    const int ig = t >> 6;

    // ldmatrix lane address components
    const int g = lane >> 3, l = lane & 7;
    const int oRow = (g & 1) * 8 + l;
    const int kHlf = (g >> 1) * 8;
    const uint32_t wAddrBase = sW + (uint32_t)(oRow * WPAD + kHlf) * 2u;
    const int kOff = (g >> 1) * 8 + l;
    const int mOff = (g & 1) * 8;
    const uint32_t bAddrBase = sB + (uint32_t)(kOff * BPAD + w * 32 + mOff) * 2u;

    float acc[2][4][4];
#pragma unroll
    for (int ot = 0; ot < 2; ++ot)
#pragma unroll
        for (int rt = 0; rt < 4; ++rt)
#pragma unroll
            for (int q = 0; q < 4; ++q) acc[ot][rt][q] = 0.0f;

    for (int c = 0; c < Q_NCH; ++c) {
        if (c) __syncthreads();          // mma(c-1) finished reading smem

        // ---- stage W chunk (8192 B): 512 uint4 blocks, 4 per thread ----
        {
            const __half* wp = g_W2 + (size_t)c * (Q_O * Q_CHK);
#pragma unroll
            for (int q = 0; q < 4; ++q) {
                int flat = q * 128 + t;          // 0..511
                int o = flat >> 4, seg = flat & 15;
                uint4 v = *reinterpret_cast<const uint4*>(wp + o * Q_CHK + seg * 8);
                *reinterpret_cast<uint4*>(smW + o * WPAD + seg * 8) = v;
            }
        }

        // ---- generate basis tile: basisT[i_local*8+(j-1)][row] ----
        {
            const float* xp = x + (size_t)(b0 + 2 * rp) * Q_I + c * Q_CHI + ig * 8;
            float xr0[8], xr1[8];
            *reinterpret_cast<float4*>(&xr0[0]) = *reinterpret_cast<const float4*>(xp);
            *reinterpret_cast<float4*>(&xr0[4]) = *reinterpret_cast<const float4*>(xp + 4);
            *reinterpret_cast<float4*>(&xr1[0]) = *reinterpret_cast<const float4*>(xp + Q_I);
            *reinterpret_cast<float4*>(&xr1[4]) = *reinterpret_cast<const float4*>(xp + Q_I + 4);
#pragma unroll
            for (int p = 0; p < 8; ++p) {
                float t0 = ftanh(xr0[p]);
                float t1 = ftanh(xr1[p]);
                float x20 = t0 + t0, x21 = t1 + t1;
                float a0 = 1.0f, b0v = 1.0f;     // U0 (folded into bias, not stored)
                float a1 = x20, b1v = x21;       // U1
                uint32_t base = sB + (uint32_t)(((ig * 8 + p) * Q_JD) * BPAD + 2 * rp) * 2u;
#pragma unroll
                for (int j = 1; j <= 8; ++j) {
                    asm volatile("st.shared.b32 [%0], %1;" :: "r"(base), "r"(pack2(a1, b1v)));
                    base += BPAD * 2;
                    if (j < 8) {
                        float a2 = fmaf(x20, a1, -a0);
                        float b2 = fmaf(x21, b1v, -b0v);
                        a0 = a1; a1 = a2; b0v = b1v; b1v = b2;
                    }
                }
            }
        }
        __syncthreads();

        // ---- MMA: 8 k16-steps ----
        uint32_t wAddr = wAddrBase;
        uint32_t bAddr = bAddrBase;
#pragma unroll
        for (int ks = 0; ks < 8; ++ks) {
            uint32_t aW0[4], aW1[4], bb0[4], bb1[4];
            ldm_x4(aW0, wAddr);                       // o 0..15
            ldm_x4(aW1, wAddr + 16u * WPAD * 2u);     // o 16..31
            ldm_x4_t(bb0, bAddr);                     // rows m0..m0+15
            ldm_x4_t(bb1, bAddr + 32u);               // rows m0+16..m0+31
            mma16816(acc[0][0], aW0, bb0[0], bb0[2]);
            mma16816(acc[1][0], aW1, bb0[0], bb0[2]);
            mma16816(acc[0][1], aW0, bb0[1], bb0[3]);
            mma16816(acc[1][1], aW1, bb0[1], bb0[3]);
            mma16816(acc[0][2], aW0, bb1[0], bb1[2]);
            mma16816(acc[1][2], aW1, bb1[0], bb1[2]);
            mma16816(acc[0][3], aW0, bb1[1], bb1[3]);
            mma16816(acc[1][3], aW1, bb1[1], bb1[3]);
            wAddr += 32u;                 // +16 halves along k
            bAddr += 16u * BPAD * 2u;     // +16 k-rows
        }
    }

    // ---- epilogue: add bias, store ----
    const int qr = lane >> 2;
    const int qc = (lane & 3) * 2;
    float bo[2][2];
#pragma unroll
    for (int ot = 0; ot < 2; ++ot) {
        bo[ot][0] = g_bias[ot * 16 + qr];
        bo[ot][1] = g_bias[ot * 16 + qr + 8];
    }
#pragma unroll
    for (int rt = 0; rt < 4; ++rt) {
        int r = b0 + 32 * w + 8 * rt + qc;
        float* po0 = out + (size_t)r * Q_O;
        float* po1 = out + (size_t)(r + 1) * Q_O;
#pragma unroll
        for (int ot = 0; ot < 2; ++ot) {
            int o = ot * 16 + qr;
            po0[o]     = acc[ot][rt][0] + bo[ot][0];
            po1[o]     = acc[ot][rt][1] + bo[ot][0];
            po0[o + 8] = acc[ot][rt][2] + bo[ot][1];
            po1[o + 8] = acc[ot][rt][3] + bo[ot][1];
        }
    }
}

extern "C" void kernel_launch(void* const* d_in, const int* in_sizes, int n_in,
                              void* d_out, int out_size) {
    const float* x  = (const float*)d_in[0];     // [65536, 512] f32
    const float* wc = (const float*)d_in[1];     // [512, 32, 9] f32
    float* out = (float*)d_out;                  // [65536, 32] f32

    int Brows = in_sizes[0] / Q_I;

    int wtot = Q_NCH * Q_O * Q_CHK;              // 131072
    repack_kernel<<<(wtot + 255) / 256, 256>>>(wc);
    bias_kernel<<<1, Q_O>>>(wc);

    cheby_mma_kernel<<<Brows / Q_ROWS, Q_THR, SM_TOT>>>(x, out);
}

// round 8
// speedup vs baseline: 1.0110x; 1.0110x over previous
#include <cuda_runtime.h>
#include <cuda_fp16.h>
#include <stdint.h>

// Problem constants
#define Q_I     512
#define Q_O     32
#define Q_JD    8                  // dense degree slots (j=1..8; j=0 folded into bias)
#define Q_CHI   16                 // inputs per chunk
#define Q_CHK   128                // k per chunk (16*8) -> 8 k16-steps (4 per k-half)
#define Q_NCH   32                 // 512/16
#define Q_ROWS  128                // batch rows per CTA
#define Q_THR   256                // 8 warps: warps 0-3 k-half 0, warps 4-7 k-half 1

// smem (halves): W [32][136] then basisT [128][136]
#define WPAD    136
#define BPAD    136
#define SM_W    0
#define SM_B    (Q_O * WPAD * 2)                  // 8704 bytes
#define SM_TOT  (SM_B + Q_CHK * BPAD * 2)         // 43520 bytes
#define RPAD    33                                 // reduction buffer row pad (f32)

// Repacked fp16 weights (j=1..8): g_W2[c][o][kl], kl = ip*8 + (j-1)
__device__ __half g_W2[Q_NCH * Q_O * Q_CHK];
__device__ float  g_bias[Q_O];

__global__ void repack_kernel(const float* __restrict__ w) {
    int idx = blockIdx.x * blockDim.x + threadIdx.x;
    if (idx >= Q_NCH * Q_O * Q_CHK) return;
    int kl = idx & 127;
    int o  = (idx >> 7) & 31;
    int c  = idx >> 12;
    int i  = c * Q_CHI + (kl >> 3);
    int j  = (kl & 7) + 1;
    g_W2[idx] = __float2half(w[(i * Q_O + o) * 9 + j]);
}

// Parallel bias: 256 threads, 8 partial sums per output, smem reduce (~1-2us)
__global__ void bias_kernel(const float* __restrict__ w) {
    __shared__ float red[256];
    int t = threadIdx.x;
    int o = t & 31, g = t >> 5;
    float s = 0.0f;
#pragma unroll 8
    for (int i = g; i < Q_I; i += 8) s += w[(i * Q_O + o) * 9];
    red[t] = s;
    __syncthreads();
    if (t < 32) {
        float tot = 0.0f;
#pragma unroll
        for (int q = 0; q < 8; ++q) tot += red[q * 32 + t];
        g_bias[t] = tot;
    }
}

// ---------------- primitives ----------------
__device__ __forceinline__ uint32_t smem_u32(const void* p) {
    uint32_t a;
    asm("{ .reg .u64 t; cvta.to.shared.u64 t, %1; cvt.u32.u64 %0, t; }" : "=r"(a) : "l"(p));
    return a;
}
__device__ __forceinline__ void ldm_x4(uint32_t (&r)[4], uint32_t addr) {
    asm volatile("ldmatrix.sync.aligned.m8n8.x4.shared.b16 {%0,%1,%2,%3}, [%4];"
                 : "=r"(r[0]), "=r"(r[1]), "=r"(r[2]), "=r"(r[3]) : "r"(addr));
}
__device__ __forceinline__ void ldm_x4_t(uint32_t (&r)[4], uint32_t addr) {
    asm volatile("ldmatrix.sync.aligned.m8n8.x4.trans.shared.b16 {%0,%1,%2,%3}, [%4];"
                 : "=r"(r[0]), "=r"(r[1]), "=r"(r[2]), "=r"(r[3]) : "r"(addr));
}
__device__ __forceinline__ void mma16816(float (&d)[4], const uint32_t (&a)[4],
                                         uint32_t b0, uint32_t b1) {
    asm volatile(
        "mma.sync.aligned.m16n8k16.row.col.f32.f16.f16.f32 "
        "{%0,%1,%2,%3}, {%4,%5,%6,%7}, {%8,%9}, {%0,%1,%2,%3};"
        : "+f"(d[0]), "+f"(d[1]), "+f"(d[2]), "+f"(d[3])
        : "r"(a[0]), "r"(a[1]), "r"(a[2]), "r"(a[3]), "r"(b0), "r"(b1));
}
// tanh(x) = 1 - 2/(exp2(2x*log2e)+1)
__device__ __forceinline__ float ftanh(float x) {
    float p;
    asm("ex2.approx.f32 %0, %1;" : "=f"(p) : "f"(x * 2.8853900817779268f));
    float r;
    asm("rcp.approx.f32 %0, %1;" : "=f"(r) : "f"(p + 1.0f));
    return fmaf(-2.0f, r, 1.0f);
}

__global__ __launch_bounds__(Q_THR)
void cheby_mma_kernel(const float* __restrict__ x, float* __restrict__ out) {
    extern __shared__ char smem[];
    const uint32_t sW = smem_u32(smem) + SM_W;
    const uint32_t sB = smem_u32(smem) + SM_B;
    __half* smW = reinterpret_cast<__half*>(smem + SM_W);

    const int t    = threadIdx.x;
    const int lane = t & 31;
    const int w    = t >> 5;             // 0..7
    const int wm   = w & 3;              // row group: rows [32wm, 32wm+32)
    const int wg   = w >> 2;             // k-half: 0 -> k 0..63, 1 -> k 64..127
    const int b0   = blockIdx.x * Q_ROWS;

    // gen mapping: thread owns ONE row, 8 inputs (32B x-load, sector-perfect)
    const int grow = 2 * (t & 63) + ((t >> 6) & 1);   // 0..127, conflict-free STS.16
    const int ig   = t >> 7;                          // 0..1 -> inputs [8ig, 8ig+8)

    // ldmatrix lane address components
    const int g = lane >> 3, l = lane & 7;
    const int oRow = (g & 1) * 8 + l;
    const int kHlf = (g >> 1) * 8;
    const uint32_t wAddrBase = sW + (uint32_t)(oRow * WPAD + kHlf + wg * 64) * 2u;
    const int kOff = (g >> 1) * 8 + l;
    const int mOff = (g & 1) * 8;
    const uint32_t bAddrBase = sB + (uint32_t)((wg * 64 + kOff) * BPAD + wm * 32 + mOff) * 2u;

    float acc[2][4][4];
#pragma unroll
    for (int ot = 0; ot < 2; ++ot)
#pragma unroll
        for (int rt = 0; rt < 4; ++rt)
#pragma unroll
            for (int q = 0; q < 4; ++q) acc[ot][rt][q] = 0.0f;

    for (int c = 0; c < Q_NCH; ++c) {
        if (c) __syncthreads();          // mma(c-1) finished reading smem

        // ---- stage W chunk (8192 B): 512 uint4 blocks, 2 per thread ----
        {
            const __half* wp = g_W2 + (size_t)c * (Q_O * Q_CHK);
#pragma unroll
            for (int q = 0; q < 2; ++q) {
                int flat = q * 256 + t;          // 0..511
                int o = flat >> 4, seg = flat & 15;
                uint4 v = *reinterpret_cast<const uint4*>(wp + o * Q_CHK + seg * 8);
                *reinterpret_cast<uint4*>(smW + o * WPAD + seg * 8) = v;
            }
        }

        // ---- generate basis: one row, 8 inputs x (j=1..8), STS.16 ----
        {
            const float* xp = x + (size_t)(b0 + grow) * Q_I + c * Q_CHI + ig * 8;
            float xr[8];
            *reinterpret_cast<float4*>(&xr[0]) = *reinterpret_cast<const float4*>(xp);
            *reinterpret_cast<float4*>(&xr[4]) = *reinterpret_cast<const float4*>(xp + 4);
#pragma unroll
            for (int p = 0; p < 8; ++p) {
                float tt = ftanh(xr[p]);
                float x2 = tt + tt;
                float a0 = 1.0f;        // U0 (folded into bias, not stored)
                float a1 = x2;          // U1
                uint32_t ad = sB + (uint32_t)(((ig * 8 + p) * Q_JD) * BPAD + grow) * 2u;
#pragma unroll
                for (int j = 1; j <= 8; ++j) {
                    __half h = __float2half_rn(a1);
                    asm volatile("st.shared.b16 [%0], %1;"
                                 :: "r"(ad), "h"(__half_as_ushort(h)));
                    ad += BPAD * 2;
                    if (j < 8) {
                        float a2 = fmaf(x2, a1, -a0);
                        a0 = a1; a1 = a2;
                    }
                }
            }
        }
        __syncthreads();

        // ---- MMA: this warp's 4 k16-steps of its k-half ----
        uint32_t wAddr = wAddrBase;
        uint32_t bAddr = bAddrBase;
#pragma unroll
        for (int ks = 0; ks < 4; ++ks) {
            uint32_t aW0[4], aW1[4], bb0[4], bb1[4];
            ldm_x4(aW0, wAddr);                       // o 0..15
            ldm_x4(aW1, wAddr + 16u * WPAD * 2u);     // o 16..31
            ldm_x4_t(bb0, bAddr);                     // rows m0..m0+15
            ldm_x4_t(bb1, bAddr + 32u);               // rows m0+16..m0+31
            mma16816(acc[0][0], aW0, bb0[0], bb0[2]);
            mma16816(acc[1][0], aW1, bb0[0], bb0[2]);
            mma16816(acc[0][1], aW0, bb0[1], bb0[3]);
            mma16816(acc[1][1], aW1, bb0[1], bb0[3]);
            mma16816(acc[0][2], aW0, bb1[0], bb1[2]);
            mma16816(acc[1][2], aW1, bb1[0], bb1[2]);
            mma16816(acc[0][3], aW0, bb1[1], bb1[3]);
            mma16816(acc[1][3], aW1, bb1[1], bb1[3]);
            wAddr += 32u;                 // +16 halves along k
            bAddr += 16u * BPAD * 2u;     // +16 k-rows
        }
    }

    // ---- split-k reduction + bias + store ----
    __syncthreads();                      // all MMAs done; smem reusable
    float* smR = reinterpret_cast<float*>(smem);      // [128][33] f32 = 16896B
    const int qr = lane >> 2;
    const int qc = (lane & 3) * 2;

    if (wg == 1) {
#pragma unroll
        for (int rt = 0; rt < 4; ++rt) {
            int r = 32 * wm + 8 * rt + qc;
#pragma unroll
            for (int ot = 0; ot < 2; ++ot) {
                int o = ot * 16 + qr;
                smR[r * RPAD + o]           = acc[ot][rt][0];
                smR[(r + 1) * RPAD + o]     = acc[ot][rt][1];
                smR[r * RPAD + o + 8]       = acc[ot][rt][2];
                smR[(r + 1) * RPAD + o + 8] = acc[ot][rt][3];
            }
        }
    }
    __syncthreads();

    if (wg == 0) {
        float bo[2][2];
#pragma unroll
        for (int ot = 0; ot < 2; ++ot) {
            bo[ot][0] = g_bias[ot * 16 + qr];
            bo[ot][1] = g_bias[ot * 16 + qr + 8];
        }
#pragma unroll
        for (int rt = 0; rt < 4; ++rt) {
            int r = 32 * wm + 8 * rt + qc;
            float* po0 = out + (size_t)(b0 + r) * Q_O;
            float* po1 = out + (size_t)(b0 + r + 1) * Q_O;
#pragma unroll
            for (int ot = 0; ot < 2; ++ot) {
                int o = ot * 16 + qr;
                po0[o]     = acc[ot][rt][0] + smR[r * RPAD + o]           + bo[ot][0];
                po1[o]     = acc[ot][rt][1] + smR[(r + 1) * RPAD + o]     + bo[ot][0];
                po0[o + 8] = acc[ot][rt][2] + smR[r * RPAD + o + 8]       + bo[ot][1];
                po1[o + 8] = acc[ot][rt][3] + smR[(r + 1) * RPAD + o + 8] + bo[ot][1];
            }
        }
    }
}

extern "C" void kernel_launch(void* const* d_in, const int* in_sizes, int n_in,
                              void* d_out, int out_size) {
    const float* x  = (const float*)d_in[0];     // [65536, 512] f32
    const float* wc = (const float*)d_in[1];     // [512, 32, 9] f32
    float* out = (float*)d_out;                  // [65536, 32] f32

    int Brows = in_sizes[0] / Q_I;

    int wtot = Q_NCH * Q_O * Q_CHK;              // 131072
    repack_kernel<<<(wtot + 255) / 256, 256>>>(wc);
    bias_kernel<<<1, 256>>>(wc);

    cheby_mma_kernel<<<Brows / Q_ROWS, Q_THR, SM_TOT>>>(x, out);
}